// round 3
// baseline (speedup 1.0000x reference)
#include <cuda_runtime.h>

#define NPOINTS     500000
#define NWAVE       128
#define NOFFSETS    50

#define TPB         256
#define WPB         (TPB / 32)          // 8 warps per block
#define NBLK        592                 // 4 blocks/SM on 148 SMs
#define NWT         (NBLK * WPB)        // 4736 total warps

#define TWO_PI      6.283185307179586f

// Per-warp partials, layout [warp][128] so accum stores are coalesced float4.
__device__ float g_partialC[NWT * NWAVE];
__device__ float g_partialS[NWT * NWAVE];
__device__ float g_m[NWAVE];

__device__ __forceinline__ void point_accum(float d, float4 t, float4 kw,
                                            float4& aC, float4& aS)
{
    float s, c;
    __sincosf(d * kw.x, &s, &c); aC.x = fmaf(c, t.x, aC.x); aS.x = fmaf(s, t.x, aS.x);
    __sincosf(d * kw.y, &s, &c); aC.y = fmaf(c, t.y, aC.y); aS.y = fmaf(s, t.y, aS.y);
    __sincosf(d * kw.z, &s, &c); aC.z = fmaf(c, t.z, aC.z); aS.z = fmaf(s, t.z, aS.z);
    __sincosf(d * kw.w, &s, &c); aC.w = fmaf(c, t.w, aC.w); aS.w = fmaf(s, t.w, aS.w);
}

__global__ __launch_bounds__(TPB, 4)
void accum_kernel(const float2* __restrict__ xy,
                  const float4* __restrict__ tid4,   // [NPOINTS][32] float4
                  const float*  __restrict__ center,
                  const float4* __restrict__ wl4)    // [32] float4
{
    const int lane = threadIdx.x & 31;
    const int gw   = blockIdx.x * WPB + (threadIdx.x >> 5);

    const float cx = center[0];
    const float cy = center[1];

    const float4 wlv = wl4[lane];
    float4 kw;
    kw.x = TWO_PI / wlv.x; kw.y = TWO_PI / wlv.y;
    kw.z = TWO_PI / wlv.z; kw.w = TWO_PI / wlv.w;

    float4 aC = make_float4(0.f, 0.f, 0.f, 0.f);
    float4 aS = make_float4(0.f, 0.f, 0.f, 0.f);
    const float4 z4 = make_float4(0.f, 0.f, 0.f, 0.f);

    // Each warp sweeps points gw, gw+NWT, ... ; 4 points per iteration for MLP.
    for (int p = gw; p < NPOINTS; p += 4 * NWT) {
        const int p1 = p + NWT, p2 = p + 2 * NWT, p3 = p + 3 * NWT;
        const bool b1 = p1 < NPOINTS, b2 = p2 < NPOINTS, b3 = p3 < NPOINTS;

        // Issue all global loads first (streaming: tid is 256MB read-once).
        const float4 t0 = __ldcs(&tid4[(size_t)p  * 32 + lane]);
        const float4 t1 = b1 ? __ldcs(&tid4[(size_t)p1 * 32 + lane]) : z4;
        const float4 t2 = b2 ? __ldcs(&tid4[(size_t)p2 * 32 + lane]) : z4;
        const float4 t3 = b3 ? __ldcs(&tid4[(size_t)p3 * 32 + lane]) : z4;

        const float2 v0 = xy[p];
        const float2 v1 = b1 ? xy[p1] : make_float2(cx, cy);
        const float2 v2 = b2 ? xy[p2] : make_float2(cx, cy);
        const float2 v3 = b3 ? xy[p3] : make_float2(cx, cy);

        float dx, dy;
        dx = v0.x - cx; dy = v0.y - cy; const float d0 = sqrtf(fmaf(dx, dx, dy * dy));
        dx = v1.x - cx; dy = v1.y - cy; const float d1 = sqrtf(fmaf(dx, dx, dy * dy));
        dx = v2.x - cx; dy = v2.y - cy; const float d2 = sqrtf(fmaf(dx, dx, dy * dy));
        dx = v3.x - cx; dy = v3.y - cy; const float d3 = sqrtf(fmaf(dx, dx, dy * dy));

        point_accum(d0, t0, kw, aC, aS);
        point_accum(d1, t1, kw, aC, aS);
        point_accum(d2, t2, kw, aC, aS);
        point_accum(d3, t3, kw, aC, aS);
    }

    // Coalesced per-warp partial store: row gw, 128 floats as 32 float4.
    ((float4*)g_partialC)[(size_t)gw * 32 + lane] = aC;
    ((float4*)g_partialS)[(size_t)gw * 32 + lane] = aS;
}

// Stage 2: one block per wavelength; reduce 4736 warp-partials (fixed order).
__global__ __launch_bounds__(256)
void reduce_kernel()
{
    __shared__ float sc[256];
    __shared__ float ss[256];

    const int w = blockIdx.x;
    const int t = threadIdx.x;

    float c = 0.0f, s = 0.0f;
    for (int b = t; b < NWT; b += 256) {      // L2-hot
        c += g_partialC[(size_t)b * NWAVE + w];
        s += g_partialS[(size_t)b * NWAVE + w];
    }
    sc[t] = c;
    ss[t] = s;
    __syncthreads();

    #pragma unroll
    for (int stride = 128; stride > 0; stride >>= 1) {
        if (t < stride) { sc[t] += sc[t + stride]; ss[t] += ss[t + stride]; }
        __syncthreads();
    }

    if (t == 0) {
        const float C = sc[0] * (1.0f / (float)NPOINTS);
        const float S = ss[0] * (1.0f / (float)NPOINTS);
        float m = -3.402823466e38f;
        #pragma unroll
        for (int i = 0; i < NOFFSETS; i++) {
            const float o = (float)i * (TWO_PI / (float)(NOFFSETS - 1));
            const float v = C * cosf(o) - S * sinf(o);
            m = fmaxf(m, v);
        }
        g_m[w] = m;
    }
}

// Stage 3: sum the 128 per-wavelength maxima, negate.
__global__ void final_sum_kernel(float* __restrict__ out)
{
    __shared__ float sm[NWAVE];
    const int w = threadIdx.x;
    sm[w] = g_m[w];
    __syncthreads();

    #pragma unroll
    for (int stride = NWAVE / 2; stride > 0; stride >>= 1) {
        if (w < stride) sm[w] += sm[w + stride];
        __syncthreads();
    }
    if (w == 0) out[0] = -sm[0];
}

extern "C" void kernel_launch(void* const* d_in, const int* in_sizes, int n_in,
                              void* d_out, int out_size)
{
    const float2* xy         = (const float2*)d_in[0];  // [500000, 2]
    const float4* tid4       = (const float4*)d_in[1];  // [500000, 128] f32
    const float*  center     = (const float*) d_in[2];  // [2]
    const float4* wl4        = (const float4*)d_in[3];  // [128] f32
    float* out = (float*)d_out;

    accum_kernel<<<NBLK, TPB>>>(xy, tid4, center, wl4);
    reduce_kernel<<<NWAVE, 256>>>();
    final_sum_kernel<<<1, NWAVE>>>(out);
}

// round 4
// speedup vs baseline: 1.6819x; 1.6819x over previous
#include <cuda_runtime.h>

#define NPOINTS     500000
#define NWAVE       128
#define NOFFSETS    50

#define TPB         128
#define NBLK        1480            // 10 blocks/SM on 148 SMs
#define TILE        128
#define QUOT        337             // NPOINTS / NBLK
#define REMR        1240            // NPOINTS - QUOT*NBLK

#define TWO_PI      6.283185307179586f

__device__ float g_partialC[NBLK * NWAVE];
__device__ float g_partialS[NBLK * NWAVE];
__device__ float g_m[NWAVE];
__device__ unsigned int g_cnt;      // zero-init; last block resets it each run

__global__ __launch_bounds__(TPB, 10)
void accum_kernel(const float2* __restrict__ xy,
                  const float*  __restrict__ tid,
                  const float*  __restrict__ center,
                  const float*  __restrict__ wavelength)
{
    __shared__ float sdist[TILE];

    const int w  = threadIdx.x;
    const float kw = TWO_PI / wavelength[w];
    const float cx = center[0];
    const float cy = center[1];

    // Balanced contiguous range: blocks differ by at most 1 point of work.
    const int b    = blockIdx.x;
    const int base = b * QUOT + min(b, REMR);
    const int cnt  = QUOT + (b < REMR ? 1 : 0);

    float accC = 0.0f;
    float accS = 0.0f;

    for (int t0 = 0; t0 < cnt; t0 += TILE) {
        const int n = min(TILE, cnt - t0);

        // Phase A: cooperatively compute dist for this tile of points.
        if (threadIdx.x < n) {
            const float2 v = xy[base + t0 + threadIdx.x];
            const float dx = v.x - cx;
            const float dy = v.y - cy;
            sdist[threadIdx.x] = sqrtf(fmaf(dx, dx, dy * dy));
        }
        __syncthreads();

        // Phase B: sweep the tile for this thread's wavelength.
        const float* __restrict__ trow = tid + (size_t)(base + t0) * NWAVE + w;

        #pragma unroll 8
        for (int i = 0; i < n; i++) {
            const float t = __ldcs(trow + (size_t)i * NWAVE);  // coalesced row read
            float s, c;
            __sincosf(sdist[i] * kw, &s, &c);                  // 2x MUFU
            accC = fmaf(c, t, accC);
            accS = fmaf(s, t, accS);
        }
        __syncthreads();
    }

    g_partialC[b * NWAVE + w] = accC;    // coalesced
    g_partialS[b * NWAVE + w] = accS;
}

// Fused stage 2+3: one block per wavelength reduces the 1480 partials
// (fixed tree order -> deterministic); the LAST block to finish also
// sums the 128 per-wavelength maxima and writes the output.
__global__ __launch_bounds__(256)
void reduce_kernel(float* __restrict__ out)
{
    __shared__ float sc[256];
    __shared__ float ss[256];
    __shared__ float sm2[NWAVE];
    __shared__ unsigned int is_last;

    const int w = blockIdx.x;
    const int t = threadIdx.x;

    float c = 0.0f, s = 0.0f;
    for (int bb = t; bb < NBLK; bb += 256) {   // L2-hot partials
        c += g_partialC[bb * NWAVE + w];
        s += g_partialS[bb * NWAVE + w];
    }
    sc[t] = c;
    ss[t] = s;
    __syncthreads();

    #pragma unroll
    for (int stride = 128; stride > 0; stride >>= 1) {
        if (t < stride) { sc[t] += sc[t + stride]; ss[t] += ss[t + stride]; }
        __syncthreads();
    }

    if (t == 0) {
        const float C = sc[0] * (1.0f / (float)NPOINTS);
        const float S = ss[0] * (1.0f / (float)NPOINTS);
        float m = -3.402823466e38f;
        #pragma unroll
        for (int i = 0; i < NOFFSETS; i++) {
            const float o = (float)i * (TWO_PI / (float)(NOFFSETS - 1));
            const float v = C * cosf(o) - S * sinf(o);
            m = fmaxf(m, v);
        }
        g_m[w] = m;
        __threadfence();
        is_last = (atomicAdd(&g_cnt, 1u) == NWAVE - 1) ? 1u : 0u;
    }
    __syncthreads();

    if (is_last) {
        if (t < NWAVE) sm2[t] = g_m[t];
        __syncthreads();
        #pragma unroll
        for (int stride = NWAVE / 2; stride > 0; stride >>= 1) {
            if (t < stride) sm2[t] += sm2[t + stride];
            __syncthreads();
        }
        if (t == 0) {
            out[0] = -sm2[0];
            g_cnt = 0;                 // reset for next graph replay
        }
    }
}

extern "C" void kernel_launch(void* const* d_in, const int* in_sizes, int n_in,
                              void* d_out, int out_size)
{
    const float2* xy         = (const float2*)d_in[0];  // [500000, 2]
    const float*  tid        = (const float*) d_in[1];  // [500000, 128]
    const float*  center     = (const float*) d_in[2];  // [2]
    const float*  wavelength = (const float*) d_in[3];  // [128]
    float* out = (float*)d_out;

    accum_kernel<<<NBLK, TPB>>>(xy, tid, center, wavelength);
    reduce_kernel<<<NWAVE, 256>>>(out);
}

// round 5
// speedup vs baseline: 1.7051x; 1.0138x over previous
#include <cuda_runtime.h>

#define NPOINTS     500000
#define NWAVE       128
#define NOFFSETS    50

#define TPB         128
#define NBLK        1480            // 10 blocks/SM on 148 SMs
#define TILE        128
#define QUOT        337             // NPOINTS / NBLK
#define REMR        1240            // NPOINTS - QUOT*NBLK

#define TWO_PI      6.283185307179586f

// Transposed layout [wave][block]: stage-2 reads are contiguous/coalesced.
__device__ float g_partialC[NWAVE * NBLK];
__device__ float g_partialS[NWAVE * NBLK];
__device__ float g_m[NWAVE];
__device__ unsigned int g_cnt;      // zero-init; last block resets it each run

__global__ __launch_bounds__(TPB, 10)
void accum_kernel(const float2* __restrict__ xy,
                  const float*  __restrict__ tid,
                  const float*  __restrict__ center,
                  const float*  __restrict__ wavelength)
{
    __shared__ float sdist[TILE];

    const int w  = threadIdx.x;
    const float kw = TWO_PI / wavelength[w];
    const float cx = center[0];
    const float cy = center[1];

    // Balanced contiguous range: blocks differ by at most 1 point of work.
    const int b    = blockIdx.x;
    const int base = b * QUOT + min(b, REMR);
    const int cnt  = QUOT + (b < REMR ? 1 : 0);

    float accC = 0.0f;
    float accS = 0.0f;

    for (int t0 = 0; t0 < cnt; t0 += TILE) {
        const int n = min(TILE, cnt - t0);

        // Phase A: cooperatively compute dist for this tile of points.
        if (threadIdx.x < n) {
            const float2 v = xy[base + t0 + threadIdx.x];
            const float dx = v.x - cx;
            const float dy = v.y - cy;
            sdist[threadIdx.x] = sqrtf(fmaf(dx, dx, dy * dy));
        }
        __syncthreads();

        // Phase B: sweep the tile for this thread's wavelength.
        const float* __restrict__ trow = tid + (size_t)(base + t0) * NWAVE + w;

        #pragma unroll 8
        for (int i = 0; i < n; i++) {
            const float t = __ldcs(trow + (size_t)i * NWAVE);  // coalesced row read
            float s, c;
            __sincosf(sdist[i] * kw, &s, &c);                  // 2x MUFU
            accC = fmaf(c, t, accC);
            accS = fmaf(s, t, accS);
        }
        __syncthreads();
    }

    // Transposed (column) store: scattered, but fire-and-forget and tiny
    // relative to the 256MB streamed above.
    g_partialC[w * NBLK + b] = accC;
    g_partialS[w * NBLK + b] = accS;
}

// Stage 2 (+fused stage 3): one block per wavelength reduces its contiguous
// row of 1480 partials with float4 coalesced loads (fixed order ->
// deterministic). Last block to finish sums the maxima and writes out.
__global__ __launch_bounds__(256)
void reduce_kernel(float* __restrict__ out)
{
    __shared__ float sc[256];
    __shared__ float ss[256];
    __shared__ float sm2[NWAVE];
    __shared__ unsigned int is_last;

    const int w = blockIdx.x;
    const int t = threadIdx.x;

    const float4* __restrict__ pc = (const float4*)(g_partialC + (size_t)w * NBLK);
    const float4* __restrict__ ps = (const float4*)(g_partialS + (size_t)w * NBLK);

    float c = 0.0f, s = 0.0f;
    #pragma unroll
    for (int i = t; i < NBLK / 4; i += 256) {   // 370 float4 rows, L2-hot
        const float4 vc = pc[i];
        const float4 vs = ps[i];
        c += (vc.x + vc.y) + (vc.z + vc.w);
        s += (vs.x + vs.y) + (vs.z + vs.w);
    }
    sc[t] = c;
    ss[t] = s;
    __syncthreads();

    #pragma unroll
    for (int stride = 128; stride > 0; stride >>= 1) {
        if (t < stride) { sc[t] += sc[t + stride]; ss[t] += ss[t + stride]; }
        __syncthreads();
    }

    if (t == 0) {
        const float C = sc[0] * (1.0f / (float)NPOINTS);
        const float S = ss[0] * (1.0f / (float)NPOINTS);
        float m = -3.402823466e38f;
        #pragma unroll
        for (int i = 0; i < NOFFSETS; i++) {
            const float o = (float)i * (TWO_PI / (float)(NOFFSETS - 1));
            const float v = C * cosf(o) - S * sinf(o);
            m = fmaxf(m, v);
        }
        g_m[w] = m;
        __threadfence();
        is_last = (atomicAdd(&g_cnt, 1u) == NWAVE - 1) ? 1u : 0u;
    }
    __syncthreads();

    if (is_last) {
        if (t < NWAVE) sm2[t] = g_m[t];
        __syncthreads();
        #pragma unroll
        for (int stride = NWAVE / 2; stride > 0; stride >>= 1) {
            if (t < stride) sm2[t] += sm2[t + stride];
            __syncthreads();
        }
        if (t == 0) {
            out[0] = -sm2[0];
            g_cnt = 0;                 // reset for next graph replay
        }
    }
}

extern "C" void kernel_launch(void* const* d_in, const int* in_sizes, int n_in,
                              void* d_out, int out_size)
{
    const float2* xy         = (const float2*)d_in[0];  // [500000, 2]
    const float*  tid        = (const float*) d_in[1];  // [500000, 128]
    const float*  center     = (const float*) d_in[2];  // [2]
    const float*  wavelength = (const float*) d_in[3];  // [128]
    float* out = (float*)d_out;

    accum_kernel<<<NBLK, TPB>>>(xy, tid, center, wavelength);
    reduce_kernel<<<NWAVE, 256>>>(out);
}